// round 15
// baseline (speedup 1.0000x reference)
#include <cuda_runtime.h>
#include <cuda_fp16.h>
#include <cstdint>
#include <math.h>

// Problem constants
#define BB     4
#define NN     4096
#define MM     32768
#define DTOK   512
#define DATOM  128
#define NHEAD  4
#define DH     32
#define WMAX   16
#define LNEPS  1e-5f

#define NTOK   (BB * NN)    // 16384 token rows
#define NATOM  (BB * MM)    // 131072 atom rows

// Single dynamic smem symbol shared by all kernels (cast locally).
extern __shared__ char dyn_smem[];

// -------- scratch (device globals; no allocations allowed) --------
__device__ __half g_K[(size_t)NATOM * DATOM];
__device__ __half g_V[(size_t)NATOM * DATOM];
__device__ float g_Q[(size_t)NTOK * DATOM];
__device__ float g_G[(size_t)NTOK * DATOM];
__device__ __half g_U[(size_t)NTOK * DATOM];
__device__ __half g_sn[(size_t)NTOK * DTOK];     // LN(s) fp16
__device__ __half g_an[(size_t)NATOM * DATOM];   // LN(a) fp16
// fp16 weights (converted once per launch by wprep_kernel)
__device__ __half g_hwk[DATOM * DATOM];
__device__ __half g_hwv[DATOM * DATOM];
__device__ __half g_hwq[DTOK * DATOM];
__device__ __half g_hwg[DTOK * DATOM];
__device__ __half g_hwo[DATOM * DTOK];

__device__ __forceinline__ float warp_sum(float v) {
#pragma unroll
    for (int o = 16; o > 0; o >>= 1) v += __shfl_xor_sync(0xffffffffu, v, o);
    return v;
}
__device__ __forceinline__ uint32_t smem_u32(const void* p) {
    uint32_t a;
    asm("{ .reg .u64 t; cvta.to.shared.u64 t, %1; cvt.u32.u64 %0, t; }"
        : "=r"(a) : "l"(p));
    return a;
}
__device__ __forceinline__ uint32_t pack_h2(float a, float b) {
    __half2 t = __floats2half2_rn(a, b);
    return *(uint32_t*)&t;
}

// ---- cp.async helpers (sm_80+) ----
#define CP_ASYNC16(dst, src) \
    asm volatile("cp.async.cg.shared.global [%0], [%1], 16;" \
                 :: "r"((uint32_t)(dst)), "l"(src))
#define CP_COMMIT() asm volatile("cp.async.commit_group;" ::: "memory")
#define CP_WAIT0()  asm volatile("cp.async.wait_group 0;" ::: "memory")

// ---- warp-level MMA helpers ----
__device__ __forceinline__ void ldm4(uint32_t* d, uint32_t addr) {
    asm volatile("ldmatrix.sync.aligned.m8n8.x4.shared.b16 {%0,%1,%2,%3}, [%4];"
                 : "=r"(d[0]), "=r"(d[1]), "=r"(d[2]), "=r"(d[3]) : "r"(addr));
}
__device__ __forceinline__ void ldm4t(uint32_t* d, uint32_t addr) {
    asm volatile("ldmatrix.sync.aligned.m8n8.x4.trans.shared.b16 {%0,%1,%2,%3}, [%4];"
                 : "=r"(d[0]), "=r"(d[1]), "=r"(d[2]), "=r"(d[3]) : "r"(addr));
}
__device__ __forceinline__ void mma16816(float* c, const uint32_t* a,
                                         uint32_t b0, uint32_t b1) {
    asm volatile(
        "mma.sync.aligned.m16n8k16.row.col.f32.f16.f16.f32 "
        "{%0,%1,%2,%3}, {%4,%5,%6,%7}, {%8,%9}, {%0,%1,%2,%3};"
        : "+f"(c[0]), "+f"(c[1]), "+f"(c[2]), "+f"(c[3])
        : "r"(a[0]), "r"(a[1]), "r"(a[2]), "r"(a[3]), "r"(b0), "r"(b1));
}

// Shared tile geometry
#define KV_STRIDE_B 272                   // bytes per smem row (136 halves)
#define KV_TILE_B   (128 * KV_STRIDE_B)   // 34816 bytes
#define STG_STRIDE_H 136                  // halves per fp16 staged row
#define STG_STRIDE_F 68                   // floats per fp32 staged row (64 cols)

#define OFF_A    0
#define OFF_B    KV_TILE_B
#define GEMM_SMEM (2 * KV_TILE_B)   // 69632 bytes

// ==================================================================
// Kernel 0: convert all weights to fp16 once.
// ==================================================================
__global__ void wprep_kernel(const float* __restrict__ wq,
                             const float* __restrict__ wk,
                             const float* __restrict__ wv,
                             const float* __restrict__ wg,
                             const float* __restrict__ wo) {
    int i = blockIdx.x * 256 + threadIdx.x;   // 0..65535
    if (i < DATOM * DATOM) {
        g_hwk[i] = __float2half_rn(wk[i]);
        g_hwv[i] = __float2half_rn(wv[i]);
    }
    g_hwq[i] = __float2half_rn(wq[i]);
    g_hwg[i] = __float2half_rn(wg[i]);
    g_hwo[i] = __float2half_rn(wo[i]);
}

// ==================================================================
// Kernel 1: LN(s) -> g_sn fp16. One warp per row of 512.
// ==================================================================
__global__ void s_prep_kernel(const float* __restrict__ s,
                              const float* __restrict__ lng,
                              const float* __restrict__ lnb) {
    int row  = blockIdx.x * 8 + (threadIdx.x >> 5);
    int lane = threadIdx.x & 31;
    const float4* p = (const float4*)(s + (size_t)row * DTOK);
    float4 v[4];
    float sum = 0.f, sq = 0.f;
#pragma unroll
    for (int j = 0; j < 4; j++) {
        v[j] = p[lane + 32 * j];
        sum += v[j].x + v[j].y + v[j].z + v[j].w;
        sq  += v[j].x * v[j].x + v[j].y * v[j].y + v[j].z * v[j].z + v[j].w * v[j].w;
    }
    sum = warp_sum(sum);
    sq  = warp_sum(sq);
    float mu = sum * (1.f / DTOK);
    float rs = rsqrtf(sq * (1.f / DTOK) - mu * mu + LNEPS);
    __half* dst = g_sn + (size_t)row * DTOK;
#pragma unroll
    for (int j = 0; j < 4; j++) {
        int c = (lane + 32 * j) * 4;
        float4 gv = *(const float4*)(lng + c);
        float4 bv = *(const float4*)(lnb + c);
        float n0 = (v[j].x - mu) * rs * gv.x + bv.x;
        float n1 = (v[j].y - mu) * rs * gv.y + bv.y;
        float n2 = (v[j].z - mu) * rs * gv.z + bv.z;
        float n3 = (v[j].w - mu) * rs * gv.w + bv.w;
        *(uint2*)(dst + c) = make_uint2(pack_h2(n0, n1), pack_h2(n2, n3));
    }
}

// ==================================================================
// Kernel 2: LN(a) -> g_an fp16. One warp per row of 128.
// ==================================================================
__global__ void a_prep_kernel(const float* __restrict__ a,
                              const float* __restrict__ lng,
                              const float* __restrict__ lnb) {
    int row  = blockIdx.x * 8 + (threadIdx.x >> 5);
    int lane = threadIdx.x & 31;
    float4 v = *(const float4*)(a + (size_t)row * DATOM + lane * 4);
    float sum = warp_sum(v.x + v.y + v.z + v.w);
    float sq  = warp_sum(v.x * v.x + v.y * v.y + v.z * v.z + v.w * v.w);
    float mu  = sum * (1.f / 128.f);
    float rs  = rsqrtf(sq * (1.f / 128.f) - mu * mu + LNEPS);
    float4 gv = ((const float4*)lng)[lane];
    float4 bv = ((const float4*)lnb)[lane];
    float n0 = (v.x - mu) * rs * gv.x + bv.x;
    float n1 = (v.y - mu) * rs * gv.y + bv.y;
    float n2 = (v.z - mu) * rs * gv.z + bv.z;
    float n3 = (v.w - mu) * rs * gv.w + bv.w;
    *(uint2*)(g_an + (size_t)row * DATOM + lane * 4) =
        make_uint2(pack_h2(n0, n1), pack_h2(n2, n3));
}

// ==================================================================
// Kernel 3: K/V GEMM, 128x64 output tile per block.
// blockIdx.y: bit0 = K/V, bit1 = column half. 3 blocks/SM.
// ==================================================================
__global__ void __launch_bounds__(256, 3)
kv_mma_kernel() {
    char* sm = dyn_smem;
    uint32_t sbase = smem_u32(sm);
    int tid = threadIdx.x;
    int warp = tid >> 5, lane = tid & 31;
    size_t rowbase = (size_t)blockIdx.x * 128;
    int sel = blockIdx.y & 1;
    int nh  = blockIdx.y >> 1;           // column half (0/1)
    const __half* w = sel ? g_hwv : g_hwk;
    __half* dst     = sel ? g_V : g_K;

    // A tile 128x128, B tile 128x64 (cols nh*64..+63)
#pragma unroll
    for (int t = 0; t < 8; t++) {
        int j   = tid + t * 256;
        int row = j >> 4;
        int c8  = (j & 15) * 8;
        CP_ASYNC16(sbase + OFF_A + (uint32_t)row * KV_STRIDE_B + c8 * 2,
                   g_an + (rowbase + row) * DATOM + c8);
    }
#pragma unroll
    for (int t = 0; t < 4; t++) {
        int j   = tid + t * 256;
        int row = j >> 3;
        int c8  = (j & 7) * 8;
        CP_ASYNC16(sbase + OFF_B + (uint32_t)row * KV_STRIDE_B + c8 * 2,
                   w + row * DATOM + nh * 64 + c8);
    }
    CP_COMMIT();
    CP_WAIT0();
    __syncthreads();

    int wm = warp & 3;    // rows wm*32..+31
    int wn = warp >> 2;   // cols wn*32..+31
    int lr = lane & 15;
    int lc = lane >> 4;
    uint32_t aAddr = sbase + OFF_A + (uint32_t)(wm * 32 + lr) * KV_STRIDE_B + lc * 16;
    uint32_t bAddr = sbase + OFF_B + (uint32_t)lr * KV_STRIDE_B + (wn * 32 + lc * 8) * 2;

    float c[2][4][4];
#pragma unroll
    for (int mt = 0; mt < 2; mt++)
#pragma unroll
        for (int nt = 0; nt < 4; nt++)
#pragma unroll
            for (int e = 0; e < 4; e++) c[mt][nt][e] = 0.f;

#pragma unroll
    for (int ks = 0; ks < 8; ks++) {
        uint32_t ak = aAddr + ks * 32;
        uint32_t bk = bAddr + ks * 16 * KV_STRIDE_B;
        uint32_t aF[2][4];
        ldm4(aF[0], ak);
        ldm4(aF[1], ak + 16 * KV_STRIDE_B);
        uint32_t b[2][4];
        ldm4t(b[0], bk);
        ldm4t(b[1], bk + 32);
#pragma unroll
        for (int mt = 0; mt < 2; mt++)
#pragma unroll
            for (int i = 0; i < 2; i++) {
                mma16816(c[mt][2 * i],     aF[mt], b[i][0], b[i][1]);
                mma16816(c[mt][2 * i + 1], aF[mt], b[i][2], b[i][3]);
            }
    }
    __syncthreads();
    {
        __half* stg = (__half*)sm;
        int cr = lane >> 2, cc2 = (lane & 3) * 2;
#pragma unroll
        for (int mt = 0; mt < 2; mt++) {
            int r0 = wm * 32 + mt * 16 + cr;
#pragma unroll
            for (int nt = 0; nt < 4; nt++) {
                int cc = wn * 32 + nt * 8 + cc2;
                *(__half2*)&stg[r0 * STG_STRIDE_H + cc] =
                    __floats2half2_rn(c[mt][nt][0], c[mt][nt][1]);
                *(__half2*)&stg[(r0 + 8) * STG_STRIDE_H + cc] =
                    __floats2half2_rn(c[mt][nt][2], c[mt][nt][3]);
            }
        }
        __syncthreads();
#pragma unroll
        for (int t = 0; t < 4; t++) {
            int j  = tid + t * 256;
            int r  = j >> 3;
            int c8 = (j & 7) * 8;
            *(uint4*)&dst[(rowbase + r) * DATOM + nh * 64 + c8] =
                *(uint4*)&stg[r * STG_STRIDE_H + c8];
        }
    }
}

// ==================================================================
// Kernel 4: Q/G GEMM, 128x64 tile. blockIdx.y: bit0 = Q/G, bit1 = half.
// K = 512 in 4 chunks. 3 blocks/SM.
// ==================================================================
__global__ void __launch_bounds__(256, 3)
qg_mma_kernel() {
    char* sm = dyn_smem;
    uint32_t sbase = smem_u32(sm);
    int tid = threadIdx.x;
    int warp = tid >> 5, lane = tid & 31;
    size_t rowbase = (size_t)blockIdx.x * 128;
    int sel = blockIdx.y & 1;
    int nh  = blockIdx.y >> 1;
    const __half* w = sel ? g_hwg : g_hwq;
    float* dst      = sel ? g_G : g_Q;

    int wm = warp & 3;
    int wn = warp >> 2;
    int lr = lane & 15;
    int lc = lane >> 4;
    uint32_t aAddr = sbase + OFF_A + (uint32_t)(wm * 32 + lr) * KV_STRIDE_B + lc * 16;
    uint32_t bAddr = sbase + OFF_B + (uint32_t)lr * KV_STRIDE_B + (wn * 32 + lc * 8) * 2;

    float c[2][4][4];
#pragma unroll
    for (int mt = 0; mt < 2; mt++)
#pragma unroll
        for (int nt = 0; nt < 4; nt++)
#pragma unroll
            for (int e = 0; e < 4; e++) c[mt][nt][e] = 0.f;

#pragma unroll 1
    for (int kc = 0; kc < 4; kc++) {
        int k0 = kc * 128;
#pragma unroll
        for (int t = 0; t < 8; t++) {
            int j   = tid + t * 256;
            int row = j >> 4;
            int c8  = (j & 15) * 8;
            CP_ASYNC16(sbase + OFF_A + (uint32_t)row * KV_STRIDE_B + c8 * 2,
                       g_sn + (rowbase + row) * DTOK + k0 + c8);
        }
#pragma unroll
        for (int t = 0; t < 4; t++) {
            int j   = tid + t * 256;
            int row = j >> 3;
            int c8  = (j & 7) * 8;
            CP_ASYNC16(sbase + OFF_B + (uint32_t)row * KV_STRIDE_B + c8 * 2,
                       w + (size_t)(k0 + row) * DATOM + nh * 64 + c8);
        }
        CP_COMMIT();
        CP_WAIT0();
        __syncthreads();
#pragma unroll
        for (int ks = 0; ks < 8; ks++) {
            uint32_t ak = aAddr + ks * 32;
            uint32_t bk = bAddr + ks * 16 * KV_STRIDE_B;
            uint32_t aF[2][4];
            ldm4(aF[0], ak);
            ldm4(aF[1], ak + 16 * KV_STRIDE_B);
            uint32_t b[2][4];
            ldm4t(b[0], bk);
            ldm4t(b[1], bk + 32);
#pragma unroll
            for (int mt = 0; mt < 2; mt++)
#pragma unroll
                for (int i = 0; i < 2; i++) {
                    mma16816(c[mt][2 * i],     aF[mt], b[i][0], b[i][1]);
                    mma16816(c[mt][2 * i + 1], aF[mt], b[i][2], b[i][3]);
                }
        }
        __syncthreads();
    }
    {
        float* stg = (float*)sm;   // 128 x 68 floats = 34816 B
        int cr = lane >> 2, cc2 = (lane & 3) * 2;
#pragma unroll
        for (int mt = 0; mt < 2; mt++) {
            int r0 = wm * 32 + mt * 16 + cr;
#pragma unroll
            for (int nt = 0; nt < 4; nt++) {
                int cc = wn * 32 + nt * 8 + cc2;
                *(float2*)&stg[r0 * STG_STRIDE_F + cc] =
                    make_float2(c[mt][nt][0], c[mt][nt][1]);
                *(float2*)&stg[(r0 + 8) * STG_STRIDE_F + cc] =
                    make_float2(c[mt][nt][2], c[mt][nt][3]);
            }
        }
        __syncthreads();
#pragma unroll
        for (int t = 0; t < 8; t++) {
            int j  = tid + t * 256;
            int r  = j >> 4;
            int c4 = (j & 15) * 4;
            *(float4*)&dst[(rowbase + r) * DATOM + nh * 64 + c4] =
                *(float4*)&stg[r * STG_STRIDE_F + c4];
        }
    }
}

// ==================================================================
// Kernel 5: ragged window attention + gate. WARP PER TOKEN.
// ==================================================================
__global__ void __launch_bounds__(256, 8)
attn_gate_kernel(const int* __restrict__ starts, const int* __restrict__ counts,
                 const float* __restrict__ tmask) {
    int warp = threadIdx.x >> 5, lane = threadIdx.x & 31;
    int bt = blockIdx.x * 8 + warp;      // token index
    int b  = bt >> 12;                   // batch (N = 4096)
    int start = starts[bt];
    int count = counts[bt];
    const float scale = 0.17677669529663687f;   // 1/sqrt(32)

    float4 q = *(const float4*)(g_Q + (size_t)bt * DATOM + lane * 4);
    const __half* kb = g_K + ((size_t)b * MM + start) * DATOM;

    float sc[WMAX];
#pragma unroll
    for (int w = 0; w < WMAX; w++) {
        float d = -1e30f;
        if (w < count) {
            uint2 raw = *(const uint2*)(kb + (size_t)w * DATOM + lane * 4);
            float2 f01 = __half22float2(*(__half2*)&raw.x);
            float2 f23 = __half22float2(*(__half2*)&raw.y);
            float t = q.x * f01.x + q.y * f01.y + q.z * f23.x + q.w * f23.y;
            t += __shfl_xor_sync(0xffffffffu, t, 1);
            t += __shfl_xor_sync(0xffffffffu, t, 2);
            t += __shfl_xor_sync(0xffffffffu, t, 4);
            d = t * scale;
        }
        sc[w] = d;
    }
    float m = -1e30f;
#pragma unroll
    for (int w = 0; w < WMAX; w++) m = fmaxf(m, sc[w]);
    float sum = 0.f;
#pragma unroll
    for (int w = 0; w < WMAX; w++) { sc[w] = expf(sc[w] - m); sum += sc[w]; }
    float inv = 1.f / sum;

    const __half* vb = g_V + ((size_t)b * MM + start) * DATOM;
    float4 acc = make_float4(0.f, 0.f, 0.f, 0.f);
#pragma unroll
    for (int w = 0; w < WMAX; w++) {
        if (w < count) {
            float p = sc[w] * inv;
            uint2 raw = *(const uint2*)(vb + (size_t)w * DATOM + lane * 4);
            float2 f01 = __half22float2(*(__half2*)&raw.x);
            float2 f23 = __half22float2(*(__half2*)&raw.y);
            acc.x = fmaf(p, f01.x, acc.x);
            acc.y = fmaf(p, f01.y, acc.y);
            acc.z = fmaf(p, f23.x, acc.z);
            acc.w = fmaf(p, f23.y, acc.w);
        }
    }
    float msk = tmask[bt];
    float4 g = *(const float4*)(g_G + (size_t)bt * DATOM + lane * 4);
    float ux = acc.x * msk / (1.f + expf(-g.x));
    float uy = acc.y * msk / (1.f + expf(-g.y));
    float uz = acc.z * msk / (1.f + expf(-g.z));
    float uw = acc.w * msk / (1.f + expf(-g.w));
    uint2 hv = make_uint2(pack_h2(ux, uy), pack_h2(uz, uw));
    *(uint2*)(g_U + (size_t)bt * DATOM + lane * 4) = hv;
}

// ==================================================================
// Kernel 6: out = U @ w_o. 128x64 tile per block (y = 0..7). 3/SM.
// ==================================================================
__global__ void __launch_bounds__(256, 3)
out_mma_kernel(float* __restrict__ out) {
    char* sm = dyn_smem;
    uint32_t sbase = smem_u32(sm);
    int tid = threadIdx.x;
    int warp = tid >> 5, lane = tid & 31;
    size_t rowbase = (size_t)blockIdx.x * 128;
    int colbase = blockIdx.y * 64;

#pragma unroll
    for (int t = 0; t < 8; t++) {
        int j   = tid + t * 256;
        int row = j >> 4;
        int c8  = (j & 15) * 8;
        CP_ASYNC16(sbase + OFF_A + (uint32_t)row * KV_STRIDE_B + c8 * 2,
                   g_U + (rowbase + row) * DATOM + c8);
    }
#pragma unroll
    for (int t = 0; t < 4; t++) {
        int j   = tid + t * 256;
        int row = j >> 3;
        int c8  = (j & 7) * 8;
        CP_ASYNC16(sbase + OFF_B + (uint32_t)row * KV_STRIDE_B + c8 * 2,
                   g_hwo + (size_t)row * DTOK + colbase + c8);
    }
    CP_COMMIT();
    CP_WAIT0();
    __syncthreads();

    int wm = warp & 3;
    int wn = warp >> 2;
    int lr = lane & 15;
    int lc = lane >> 4;
    uint32_t aAddr = sbase + OFF_A + (uint32_t)(wm * 32 + lr) * KV_STRIDE_B + lc * 16;
    uint32_t bAddr = sbase + OFF_B + (uint32_t)lr * KV_STRIDE_B + (wn * 32 + lc * 8) * 2;

    float c[2][4][4];
#pragma unroll
    for (int mt = 0; mt < 2; mt++)
#pragma unroll
        for (int nt = 0; nt < 4; nt++)
#pragma unroll
            for (int e = 0; e < 4; e++) c[mt][nt][e] = 0.f;

#pragma unroll
    for (int ks = 0; ks < 8; ks++) {
        uint32_t ak = aAddr + ks * 32;
        uint32_t bk = bAddr + ks * 16 * KV_STRIDE_B;
        uint32_t aF[2][4];
        ldm4(aF[0], ak);
        ldm4(aF[1], ak + 16 * KV_STRIDE_B);
        uint32_t b[2][4];
        ldm4t(b[0], bk);
        ldm4t(b[1], bk + 32);
#pragma unroll
        for (int mt = 0; mt < 2; mt++)
#pragma unroll
            for (int i = 0; i < 2; i++) {
                mma16816(c[mt][2 * i],     aF[mt], b[i][0], b[i][1]);
                mma16816(c[mt][2 * i + 1], aF[mt], b[i][2], b[i][3]);
            }
    }
    __syncthreads();
    {
        float* stg = (float*)sm;
        int cr = lane >> 2, cc2 = (lane & 3) * 2;
#pragma unroll
        for (int mt = 0; mt < 2; mt++) {
            int r0 = wm * 32 + mt * 16 + cr;
#pragma unroll
            for (int nt = 0; nt < 4; nt++) {
                int cc = wn * 32 + nt * 8 + cc2;
                *(float2*)&stg[r0 * STG_STRIDE_F + cc] =
                    make_float2(c[mt][nt][0], c[mt][nt][1]);
                *(float2*)&stg[(r0 + 8) * STG_STRIDE_F + cc] =
                    make_float2(c[mt][nt][2], c[mt][nt][3]);
            }
        }
        __syncthreads();
#pragma unroll
        for (int t = 0; t < 8; t++) {
            int j  = tid + t * 256;
            int r  = j >> 4;
            int c4 = (j & 15) * 4;
            *(float4*)&out[(rowbase + r) * DTOK + colbase + c4] =
                *(float4*)&stg[r * STG_STRIDE_F + c4];
        }
    }
}

// ==================================================================
// Launch.
// ==================================================================
extern "C" void kernel_launch(void* const* d_in, const int* in_sizes, int n_in,
                              void* d_out, int out_size) {
    const float* s      = (const float*)d_in[0];
    const float* a      = (const float*)d_in[1];
    const int*   starts = (const int*)  d_in[2];
    const int*   counts = (const int*)  d_in[3];
    const float* tmask  = (const float*)d_in[4];
    const float* wq     = (const float*)d_in[5];
    const float* wk     = (const float*)d_in[6];
    const float* wv     = (const float*)d_in[7];
    const float* wg     = (const float*)d_in[8];
    const float* wo     = (const float*)d_in[9];
    const float* lnqg   = (const float*)d_in[10];
    const float* lnqb   = (const float*)d_in[11];
    const float* lnkg   = (const float*)d_in[12];
    const float* lnkb   = (const float*)d_in[13];
    float* out = (float*)d_out;

    cudaFuncSetAttribute(kv_mma_kernel,
                         cudaFuncAttributeMaxDynamicSharedMemorySize, GEMM_SMEM);
    cudaFuncSetAttribute(qg_mma_kernel,
                         cudaFuncAttributeMaxDynamicSharedMemorySize, GEMM_SMEM);
    cudaFuncSetAttribute(out_mma_kernel,
                         cudaFuncAttributeMaxDynamicSharedMemorySize, GEMM_SMEM);

    wprep_kernel<<<256, 256>>>(wq, wk, wv, wg, wo);
    s_prep_kernel<<<NTOK / 8, 256>>>(s, lnqg, lnqb);
    a_prep_kernel<<<NATOM / 8, 256>>>(a, lnkg, lnkb);
    kv_mma_kernel<<<dim3(NATOM / 128, 4), 256, GEMM_SMEM>>>();
    qg_mma_kernel<<<dim3(NTOK / 128, 4), 256, GEMM_SMEM>>>();
    attn_gate_kernel<<<NTOK / 8, 256>>>(starts, counts, tmask);
    out_mma_kernel<<<dim3(NTOK / 128, 8), 256, GEMM_SMEM>>>(out);
}

// round 16
// speedup vs baseline: 1.0323x; 1.0323x over previous
#include <cuda_runtime.h>
#include <cuda_fp16.h>
#include <cstdint>
#include <math.h>

// Problem constants
#define BB     4
#define NN     4096
#define MM     32768
#define DTOK   512
#define DATOM  128
#define NHEAD  4
#define DH     32
#define WMAX   16
#define LNEPS  1e-5f

#define NTOK   (BB * NN)    // 16384 token rows
#define NATOM  (BB * MM)    // 131072 atom rows

extern __shared__ char dyn_smem[];

// -------- scratch (device globals; no allocations allowed) --------
__device__ __half g_K[(size_t)NATOM * DATOM];
__device__ __half g_V[(size_t)NATOM * DATOM];
__device__ float g_Q[(size_t)NTOK * DATOM];
__device__ float g_G[(size_t)NTOK * DATOM];
__device__ __half g_U[(size_t)NTOK * DATOM];
__device__ __half g_sn[(size_t)NTOK * DTOK];     // LN(s) fp16
__device__ __half g_an[(size_t)NATOM * DATOM];   // LN(a) fp16
__device__ __half g_hwk[DATOM * DATOM];
__device__ __half g_hwv[DATOM * DATOM];
__device__ __half g_hwq[DTOK * DATOM];
__device__ __half g_hwg[DTOK * DATOM];
__device__ __half g_hwo[DATOM * DTOK];

__device__ __forceinline__ float warp_sum(float v) {
#pragma unroll
    for (int o = 16; o > 0; o >>= 1) v += __shfl_xor_sync(0xffffffffu, v, o);
    return v;
}
__device__ __forceinline__ uint32_t smem_u32(const void* p) {
    uint32_t a;
    asm("{ .reg .u64 t; cvta.to.shared.u64 t, %1; cvt.u32.u64 %0, t; }"
        : "=r"(a) : "l"(p));
    return a;
}
__device__ __forceinline__ uint32_t pack_h2(float a, float b) {
    __half2 t = __floats2half2_rn(a, b);
    return *(uint32_t*)&t;
}

// ---- cp.async helpers ----
#define CP_ASYNC16(dst, src) \
    asm volatile("cp.async.cg.shared.global [%0], [%1], 16;" \
                 :: "r"((uint32_t)(dst)), "l"(src))
#define CP_COMMIT() asm volatile("cp.async.commit_group;" ::: "memory")
#define CP_WAIT0()  asm volatile("cp.async.wait_group 0;" ::: "memory")

// ---- warp-level MMA helpers ----
__device__ __forceinline__ void ldm4(uint32_t* d, uint32_t addr) {
    asm volatile("ldmatrix.sync.aligned.m8n8.x4.shared.b16 {%0,%1,%2,%3}, [%4];"
                 : "=r"(d[0]), "=r"(d[1]), "=r"(d[2]), "=r"(d[3]) : "r"(addr));
}
__device__ __forceinline__ void ldm4t(uint32_t* d, uint32_t addr) {
    asm volatile("ldmatrix.sync.aligned.m8n8.x4.trans.shared.b16 {%0,%1,%2,%3}, [%4];"
                 : "=r"(d[0]), "=r"(d[1]), "=r"(d[2]), "=r"(d[3]) : "r"(addr));
}
__device__ __forceinline__ void mma16816(float* c, const uint32_t* a,
                                         uint32_t b0, uint32_t b1) {
    asm volatile(
        "mma.sync.aligned.m16n8k16.row.col.f32.f16.f16.f32 "
        "{%0,%1,%2,%3}, {%4,%5,%6,%7}, {%8,%9}, {%0,%1,%2,%3};"
        : "+f"(c[0]), "+f"(c[1]), "+f"(c[2]), "+f"(c[3])
        : "r"(a[0]), "r"(a[1]), "r"(a[2]), "r"(a[3]), "r"(b0), "r"(b1));
}

// Shared tile geometry (128x128 fp16 tiles, padded)
#define KV_STRIDE_B 272
#define KV_TILE_B   (128 * KV_STRIDE_B)   // 34816 bytes
#define STG_STRIDE  136                   // floats per staged row
#define STG_STRIDE_H 136                  // halves per staged row

#define OFF_A    0
#define OFF_B    KV_TILE_B
#define GEMM_SMEM (2 * KV_TILE_B)   // 69632 bytes

// prep_all block ranges
#define PREP_W   256
#define PREP_S   2048
#define PREP_A   16384
#define PREP_BLOCKS (PREP_W + PREP_S + PREP_A)

// gemm_kvqg block ranges: kv = 2048 (1024 x-tiles * 2 sel), qg = 256
#define KV_BLOCKS 2048
#define GEMM_BLOCKS (KV_BLOCKS + 256)

// ==================================================================
// Kernel 1: ALL preps in one launch (independent work, block ranges).
// ==================================================================
__global__ void prep_all_kernel(const float* __restrict__ s,
                                const float* __restrict__ a,
                                const float* __restrict__ wq,
                                const float* __restrict__ wk,
                                const float* __restrict__ wv,
                                const float* __restrict__ wg,
                                const float* __restrict__ wo,
                                const float* __restrict__ lnqg,
                                const float* __restrict__ lnqb,
                                const float* __restrict__ lnkg,
                                const float* __restrict__ lnkb) {
    int blk = blockIdx.x;
    int tid = threadIdx.x;
    if (blk < PREP_W) {
        // ---- weight fp16 conversion ----
        int i = blk * 256 + tid;
        if (i < DATOM * DATOM) {
            g_hwk[i] = __float2half_rn(wk[i]);
            g_hwv[i] = __float2half_rn(wv[i]);
        }
        g_hwq[i] = __float2half_rn(wq[i]);
        g_hwg[i] = __float2half_rn(wg[i]);
        g_hwo[i] = __float2half_rn(wo[i]);
    } else if (blk < PREP_W + PREP_S) {
        // ---- LN(s) -> g_sn ----
        int row  = (blk - PREP_W) * 8 + (tid >> 5);
        int lane = tid & 31;
        const float4* p = (const float4*)(s + (size_t)row * DTOK);
        float4 v[4];
        float sum = 0.f, sq = 0.f;
#pragma unroll
        for (int j = 0; j < 4; j++) {
            v[j] = p[lane + 32 * j];
            sum += v[j].x + v[j].y + v[j].z + v[j].w;
            sq  += v[j].x * v[j].x + v[j].y * v[j].y + v[j].z * v[j].z + v[j].w * v[j].w;
        }
        sum = warp_sum(sum);
        sq  = warp_sum(sq);
        float mu = sum * (1.f / DTOK);
        float rs = rsqrtf(sq * (1.f / DTOK) - mu * mu + LNEPS);
        __half* dst = g_sn + (size_t)row * DTOK;
#pragma unroll
        for (int j = 0; j < 4; j++) {
            int c = (lane + 32 * j) * 4;
            float4 gv = *(const float4*)(lnqg + c);
            float4 bv = *(const float4*)(lnqb + c);
            float n0 = (v[j].x - mu) * rs * gv.x + bv.x;
            float n1 = (v[j].y - mu) * rs * gv.y + bv.y;
            float n2 = (v[j].z - mu) * rs * gv.z + bv.z;
            float n3 = (v[j].w - mu) * rs * gv.w + bv.w;
            *(uint2*)(dst + c) = make_uint2(pack_h2(n0, n1), pack_h2(n2, n3));
        }
    } else {
        // ---- LN(a) -> g_an ----
        int row  = (blk - PREP_W - PREP_S) * 8 + (tid >> 5);
        int lane = tid & 31;
        float4 v = *(const float4*)(a + (size_t)row * DATOM + lane * 4);
        float sum = warp_sum(v.x + v.y + v.z + v.w);
        float sq  = warp_sum(v.x * v.x + v.y * v.y + v.z * v.z + v.w * v.w);
        float mu  = sum * (1.f / 128.f);
        float rs  = rsqrtf(sq * (1.f / 128.f) - mu * mu + LNEPS);
        float4 gv = ((const float4*)lnkg)[lane];
        float4 bv = ((const float4*)lnkb)[lane];
        float n0 = (v.x - mu) * rs * gv.x + bv.x;
        float n1 = (v.y - mu) * rs * gv.y + bv.y;
        float n2 = (v.z - mu) * rs * gv.z + bv.z;
        float n3 = (v.w - mu) * rs * gv.w + bv.w;
        *(uint2*)(g_an + (size_t)row * DATOM + lane * 4) =
            make_uint2(pack_h2(n0, n1), pack_h2(n2, n3));
    }
}

// ==================================================================
// GEMM bodies (R13 shapes, proven), inlined into one merged kernel.
// ==================================================================
__device__ __forceinline__ void kv_body(int bx, char* sm, uint32_t sbase) {
    int tid = threadIdx.x;
    int warp = tid >> 5, lane = tid & 31;
    int sel = bx & 1;
    size_t rowbase = (size_t)(bx >> 1) * 128;
    const __half* w = sel ? g_hwv : g_hwk;
    __half* dst     = sel ? g_V : g_K;

#pragma unroll
    for (int t = 0; t < 8; t++) {
        int j   = tid + t * 256;
        int row = j >> 4;
        int c8  = (j & 15) * 8;
        uint32_t off = (uint32_t)row * KV_STRIDE_B + c8 * 2;
        CP_ASYNC16(sbase + OFF_A + off, g_an + (rowbase + row) * DATOM + c8);
        CP_ASYNC16(sbase + OFF_B + off, w + row * DATOM + c8);
    }
    CP_COMMIT();
    CP_WAIT0();
    __syncthreads();

    int wm = warp & 3;
    int wn = warp >> 2;
    int lr = lane & 15;
    int lc = lane >> 4;
    uint32_t aAddr = sbase + OFF_A + (uint32_t)(wm * 32 + lr) * KV_STRIDE_B + lc * 16;
    uint32_t bAddr = sbase + OFF_B + (uint32_t)lr * KV_STRIDE_B + (wn * 64 + lc * 8) * 2;

    float c[2][8][4];
#pragma unroll
    for (int mt = 0; mt < 2; mt++)
#pragma unroll
        for (int nt = 0; nt < 8; nt++)
#pragma unroll
            for (int e = 0; e < 4; e++) c[mt][nt][e] = 0.f;

#pragma unroll
    for (int ks = 0; ks < 8; ks++) {
        uint32_t ak = aAddr + ks * 32;
        uint32_t bk = bAddr + ks * 16 * KV_STRIDE_B;
        uint32_t aF[2][4];
        ldm4(aF[0], ak);
        ldm4(aF[1], ak + 16 * KV_STRIDE_B);
        uint32_t b[4][4];
#pragma unroll
        for (int i = 0; i < 4; i++) ldm4t(b[i], bk + i * 32);
#pragma unroll
        for (int mt = 0; mt < 2; mt++)
#pragma unroll
            for (int i = 0; i < 4; i++) {
                mma16816(c[mt][2 * i],     aF[mt], b[i][0], b[i][1]);
                mma16816(c[mt][2 * i + 1], aF[mt], b[i][2], b[i][3]);
            }
    }
    __syncthreads();
    {
        __half* stg = (__half*)(sm + OFF_A);
        int cr = lane >> 2, cc2 = (lane & 3) * 2;
#pragma unroll
        for (int mt = 0; mt < 2; mt++) {
            int r0 = wm * 32 + mt * 16 + cr;
#pragma unroll
            for (int nt = 0; nt < 8; nt++) {
                int cc = wn * 64 + nt * 8 + cc2;
                *(__half2*)&stg[r0 * STG_STRIDE_H + cc] =
                    __floats2half2_rn(c[mt][nt][0], c[mt][nt][1]);
                *(__half2*)&stg[(r0 + 8) * STG_STRIDE_H + cc] =
                    __floats2half2_rn(c[mt][nt][2], c[mt][nt][3]);
            }
        }
        __syncthreads();
#pragma unroll
        for (int t = 0; t < 8; t++) {
            int j  = tid + t * 256;
            int r  = j >> 4;
            int c8 = (j & 15) * 8;
            *(uint4*)&dst[(rowbase + r) * DATOM + c8] =
                *(uint4*)&stg[r * STG_STRIDE_H + c8];
        }
    }
}

__device__ __forceinline__ void qg_body(int bx, char* sm, uint32_t sbase) {
    int tid = threadIdx.x;
    int warp = tid >> 5, lane = tid & 31;
    int sel = bx & 1;
    size_t rowbase = (size_t)(bx >> 1) * 128;
    const __half* w = sel ? g_hwg : g_hwq;
    float* dst      = sel ? g_G : g_Q;

    int wm = warp & 3;
    int wn = warp >> 2;
    int lr = lane & 15;
    int lc = lane >> 4;
    uint32_t aAddr = sbase + OFF_A + (uint32_t)(wm * 32 + lr) * KV_STRIDE_B + lc * 16;
    uint32_t bAddr = sbase + OFF_B + (uint32_t)lr * KV_STRIDE_B + (wn * 64 + lc * 8) * 2;

    float c[2][8][4];
#pragma unroll
    for (int mt = 0; mt < 2; mt++)
#pragma unroll
        for (int nt = 0; nt < 8; nt++)
#pragma unroll
            for (int e = 0; e < 4; e++) c[mt][nt][e] = 0.f;

#pragma unroll 1
    for (int kc = 0; kc < 4; kc++) {
        int k0 = kc * 128;
#pragma unroll
        for (int t = 0; t < 8; t++) {
            int j   = tid + t * 256;
            int row = j >> 4;
            int c8  = (j & 15) * 8;
            uint32_t off = (uint32_t)row * KV_STRIDE_B + c8 * 2;
            CP_ASYNC16(sbase + OFF_A + off,
                       g_sn + (rowbase + row) * DTOK + k0 + c8);
            CP_ASYNC16(sbase + OFF_B + off,
                       w + (size_t)(k0 + row) * DATOM + c8);
        }
        CP_COMMIT();
        CP_WAIT0();
        __syncthreads();
#pragma unroll
        for (int ks = 0; ks < 8; ks++) {
            uint32_t ak = aAddr + ks * 32;
            uint32_t bk = bAddr + ks * 16 * KV_STRIDE_B;
            uint32_t aF[2][4];
            ldm4(aF[0], ak);
            ldm4(aF[1], ak + 16 * KV_STRIDE_B);
            uint32_t b[4][4];
#pragma unroll
            for (int i = 0; i < 4; i++) ldm4t(b[i], bk + i * 32);
#pragma unroll
            for (int mt = 0; mt < 2; mt++)
#pragma unroll
                for (int i = 0; i < 4; i++) {
                    mma16816(c[mt][2 * i],     aF[mt], b[i][0], b[i][1]);
                    mma16816(c[mt][2 * i + 1], aF[mt], b[i][2], b[i][3]);
                }
        }
        __syncthreads();
    }
    {
        float* stg = (float*)sm;
        int cr = lane >> 2, cc2 = (lane & 3) * 2;
#pragma unroll
        for (int mt = 0; mt < 2; mt++) {
            int r0 = wm * 32 + mt * 16 + cr;
#pragma unroll
            for (int nt = 0; nt < 8; nt++) {
                int cc = wn * 64 + nt * 8 + cc2;
                *(float2*)&stg[r0 * STG_STRIDE + cc] =
                    make_float2(c[mt][nt][0], c[mt][nt][1]);
                *(float2*)&stg[(r0 + 8) * STG_STRIDE + cc] =
                    make_float2(c[mt][nt][2], c[mt][nt][3]);
            }
        }
        __syncthreads();
#pragma unroll
        for (int t = 0; t < 16; t++) {
            int j  = tid + t * 256;
            int r  = j >> 5;
            int c4 = (j & 31) * 4;
            *(float4*)&dst[(rowbase + r) * DATOM + c4] =
                *(float4*)&stg[r * STG_STRIDE + c4];
        }
    }
}

// ==================================================================
// Kernel 2: kv + qg in ONE launch (blocks overlap on the chip).
// ==================================================================
__global__ void __launch_bounds__(256, 2)
gemm_kvqg_kernel() {
    char* sm = dyn_smem;
    uint32_t sbase = smem_u32(sm);
    int bx = blockIdx.x;
    if (bx < KV_BLOCKS) kv_body(bx, sm, sbase);
    else                qg_body(bx - KV_BLOCKS, sm, sbase);
}

// ==================================================================
// Kernel 3: ragged window attention + gate. WARP PER TOKEN.
// ==================================================================
__global__ void __launch_bounds__(256, 8)
attn_gate_kernel(const int* __restrict__ starts, const int* __restrict__ counts,
                 const float* __restrict__ tmask) {
    int warp = threadIdx.x >> 5, lane = threadIdx.x & 31;
    int bt = blockIdx.x * 8 + warp;
    int b  = bt >> 12;
    int start = starts[bt];
    int count = counts[bt];
    const float scale = 0.17677669529663687f;

    float4 q = *(const float4*)(g_Q + (size_t)bt * DATOM + lane * 4);
    const __half* kb = g_K + ((size_t)b * MM + start) * DATOM;

    float sc[WMAX];
#pragma unroll
    for (int w = 0; w < WMAX; w++) {
        float d = -1e30f;
        if (w < count) {
            uint2 raw = *(const uint2*)(kb + (size_t)w * DATOM + lane * 4);
            float2 f01 = __half22float2(*(__half2*)&raw.x);
            float2 f23 = __half22float2(*(__half2*)&raw.y);
            float t = q.x * f01.x + q.y * f01.y + q.z * f23.x + q.w * f23.y;
            t += __shfl_xor_sync(0xffffffffu, t, 1);
            t += __shfl_xor_sync(0xffffffffu, t, 2);
            t += __shfl_xor_sync(0xffffffffu, t, 4);
            d = t * scale;
        }
        sc[w] = d;
    }
    float m = -1e30f;
#pragma unroll
    for (int w = 0; w < WMAX; w++) m = fmaxf(m, sc[w]);
    float sum = 0.f;
#pragma unroll
    for (int w = 0; w < WMAX; w++) { sc[w] = expf(sc[w] - m); sum += sc[w]; }
    float inv = 1.f / sum;

    const __half* vb = g_V + ((size_t)b * MM + start) * DATOM;
    float4 acc = make_float4(0.f, 0.f, 0.f, 0.f);
#pragma unroll
    for (int w = 0; w < WMAX; w++) {
        if (w < count) {
            float p = sc[w] * inv;
            uint2 raw = *(const uint2*)(vb + (size_t)w * DATOM + lane * 4);
            float2 f01 = __half22float2(*(__half2*)&raw.x);
            float2 f23 = __half22float2(*(__half2*)&raw.y);
            acc.x = fmaf(p, f01.x, acc.x);
            acc.y = fmaf(p, f01.y, acc.y);
            acc.z = fmaf(p, f23.x, acc.z);
            acc.w = fmaf(p, f23.y, acc.w);
        }
    }
    float msk = tmask[bt];
    float4 g = *(const float4*)(g_G + (size_t)bt * DATOM + lane * 4);
    float ux = acc.x * msk / (1.f + expf(-g.x));
    float uy = acc.y * msk / (1.f + expf(-g.y));
    float uz = acc.z * msk / (1.f + expf(-g.z));
    float uw = acc.w * msk / (1.f + expf(-g.w));
    uint2 hv = make_uint2(pack_h2(ux, uy), pack_h2(uz, uw));
    *(uint2*)(g_U + (size_t)bt * DATOM + lane * 4) = hv;
}

// ==================================================================
// Kernel 4: out = U @ w_o. One 128-col quarter per block (y = 0..3).
// ==================================================================
__global__ void __launch_bounds__(256, 2)
out_mma_kernel(float* __restrict__ out) {
    char* sm = dyn_smem;
    uint32_t sbase = smem_u32(sm);
    int tid = threadIdx.x;
    int warp = tid >> 5, lane = tid & 31;
    size_t rowbase = (size_t)blockIdx.x * 128;
    int colbase = blockIdx.y * 128;

#pragma unroll
    for (int t = 0; t < 8; t++) {
        int j   = tid + t * 256;
        int row = j >> 4;
        int c8  = (j & 15) * 8;
        uint32_t off = (uint32_t)row * KV_STRIDE_B + c8 * 2;
        CP_ASYNC16(sbase + OFF_A + off, g_U + (rowbase + row) * DATOM + c8);
        CP_ASYNC16(sbase + OFF_B + off,
                   g_hwo + (size_t)row * DTOK + colbase + c8);
    }
    CP_COMMIT();
    CP_WAIT0();
    __syncthreads();

    int wm = warp & 3;
    int wn = warp >> 2;
    int lr = lane & 15;
    int lc = lane >> 4;
    uint32_t aAddr = sbase + OFF_A + (uint32_t)(wm * 32 + lr) * KV_STRIDE_B + lc * 16;
    uint32_t bAddr = sbase + OFF_B + (uint32_t)lr * KV_STRIDE_B + (wn * 64 + lc * 8) * 2;

    float c[2][8][4];
#pragma unroll
    for (int mt = 0; mt < 2; mt++)
#pragma unroll
        for (int nt = 0; nt < 8; nt++)
#pragma unroll
            for (int e = 0; e < 4; e++) c[mt][nt][e] = 0.f;

#pragma unroll
    for (int ks = 0; ks < 8; ks++) {
        uint32_t ak = aAddr + ks * 32;
        uint32_t bk = bAddr + ks * 16 * KV_STRIDE_B;
        uint32_t aF[2][4];
        ldm4(aF[0], ak);
        ldm4(aF[1], ak + 16 * KV_STRIDE_B);
        uint32_t b[4][4];
#pragma unroll
        for (int i = 0; i < 4; i++) ldm4t(b[i], bk + i * 32);
#pragma unroll
        for (int mt = 0; mt < 2; mt++)
#pragma unroll
            for (int i = 0; i < 4; i++) {
                mma16816(c[mt][2 * i],     aF[mt], b[i][0], b[i][1]);
                mma16816(c[mt][2 * i + 1], aF[mt], b[i][2], b[i][3]);
            }
    }
    __syncthreads();
    {
        float* stg = (float*)sm;
        int cr = lane >> 2, cc2 = (lane & 3) * 2;
#pragma unroll
        for (int mt = 0; mt < 2; mt++) {
            int r0 = wm * 32 + mt * 16 + cr;
#pragma unroll
            for (int nt = 0; nt < 8; nt++) {
                int cc = wn * 64 + nt * 8 + cc2;
                *(float2*)&stg[r0 * STG_STRIDE + cc] =
                    make_float2(c[mt][nt][0], c[mt][nt][1]);
                *(float2*)&stg[(r0 + 8) * STG_STRIDE + cc] =
                    make_float2(c[mt][nt][2], c[mt][nt][3]);
            }
        }
        __syncthreads();
#pragma unroll
        for (int t = 0; t < 16; t++) {
            int j  = tid + t * 256;
            int r  = j >> 5;
            int c4 = (j & 31) * 4;
            *(float4*)&out[(rowbase + r) * DTOK + colbase + c4] =
                *(float4*)&stg[r * STG_STRIDE + c4];
        }
    }
}

// ==================================================================
// Launch.
// ==================================================================
extern "C" void kernel_launch(void* const* d_in, const int* in_sizes, int n_in,
                              void* d_out, int out_size) {
    const float* s      = (const float*)d_in[0];
    const float* a      = (const float*)d_in[1];
    const int*   starts = (const int*)  d_in[2];
    const int*   counts = (const int*)  d_in[3];
    const float* tmask  = (const float*)d_in[4];
    const float* wq     = (const float*)d_in[5];
    const float* wk     = (const float*)d_in[6];
    const float* wv     = (const float*)d_in[7];
    const float* wg     = (const float*)d_in[8];
    const float* wo     = (const float*)d_in[9];
    const float* lnqg   = (const float*)d_in[10];
    const float* lnqb   = (const float*)d_in[11];
    const float* lnkg   = (const float*)d_in[12];
    const float* lnkb   = (const float*)d_in[13];
    float* out = (float*)d_out;

    cudaFuncSetAttribute(gemm_kvqg_kernel,
                         cudaFuncAttributeMaxDynamicSharedMemorySize, GEMM_SMEM);
    cudaFuncSetAttribute(out_mma_kernel,
                         cudaFuncAttributeMaxDynamicSharedMemorySize, GEMM_SMEM);

    prep_all_kernel<<<PREP_BLOCKS, 256>>>(s, a, wq, wk, wv, wg, wo,
                                          lnqg, lnqb, lnkg, lnkb);
    gemm_kvqg_kernel<<<GEMM_BLOCKS, 256, GEMM_SMEM>>>();
    attn_gate_kernel<<<NTOK / 8, 256>>>(starts, counts, tmask);
    out_mma_kernel<<<dim3(NTOK / 128, 4), 256, GEMM_SMEM>>>(out);
}